// round 14
// baseline (speedup 1.0000x reference)
#include <cuda_runtime.h>
#include <cuda_fp16.h>
#include <math.h>
#include <stddef.h>
#include <stdint.h>

#define N1 262144
#define N2 65536
#define N3 16384
#define E1 524288
#define E2 262144
#define IN_DIM 128
#define HID 64
#define HEADS 4
#define HD 256
#define OUT_DIM 64
#define NEG_SLOPE 0.2f
#define BN_EPS 1e-5f

// ---------------- scratch (device globals: zero-initialized at load) -------
__device__ __align__(16) float  g_V1s[IN_DIM * HEADS];   // [k][h]
__device__ __align__(16) float  g_V1d[IN_DIM * HEADS];
__device__ __align__(16) float  g_V2s[HD];
__device__ __align__(16) float  g_V2d[HD];
__device__ __align__(16) float  g_bnsc[HD];
__device__ __align__(16) float  g_bnsh[HD];
__device__ __align__(16) __half g_W1hT[HD * IN_DIM];     // [n][k] fp16 W1_src^T

__device__ __align__(16) float  g_a1s[N1 * HEADS];
__device__ __align__(16) float  g_a1d[N2 * HEADS];
__device__ __align__(16) __half g_xh[(size_t)N1 * IN_DIM];            // 67 MB
__device__ __align__(16) __half g_agg1h[(size_t)N2 * HEADS * IN_DIM]; // 67 MB
__device__ __align__(16) __half g_h1h[(size_t)N2 * HD];               // 33 MB

__device__ __align__(16) float g_a2sp[N2 * HEADS];   // [row*4+head]
__device__ __align__(16) float g_a2dp[N3 * HEADS];   // [row*4+head]
__device__ __align__(16) float g_agg2[(size_t)N3 * HD];               // 16 MB

// CSR-by-dst scratch (zero-init counts; re-zeroed per run inside scatter)
__device__ __align__(16) int    g_cnt1[N2];
__device__ __align__(16) int    g_rs1[N2 + 4];
__device__ __align__(16) int    g_cur1[N2];
__device__ __align__(16) int    g_srcs1[E1];
__device__ __align__(16) float4 g_p1[E1];            // per-edge softmax numerators
__device__ __align__(16) int    g_cnt2[N3];
__device__ __align__(16) int    g_rs2[N3 + 4];
__device__ __align__(16) int    g_cur2[N3];
__device__ __align__(16) int    g_srcs2[E2];

// ---------------- helpers ----------------
__device__ __forceinline__ float wredsum(float v) {
    #pragma unroll
    for (int o = 16; o; o >>= 1) v += __shfl_xor_sync(0xFFFFFFFFu, v, o);
    return v;
}
__device__ __forceinline__ void ldsm_x4(uint32_t& r0, uint32_t& r1, uint32_t& r2,
                                        uint32_t& r3, uint32_t addr) {
    asm volatile("ldmatrix.sync.aligned.m8n8.x4.shared.b16 {%0,%1,%2,%3}, [%4];"
                 : "=r"(r0), "=r"(r1), "=r"(r2), "=r"(r3) : "r"(addr));
}
__device__ __forceinline__ void mma16816(float* d, uint32_t a0, uint32_t a1,
                                         uint32_t a2, uint32_t a3,
                                         uint32_t b0, uint32_t b1) {
    asm volatile("mma.sync.aligned.m16n8k16.row.col.f32.f16.f16.f32 "
                 "{%0,%1,%2,%3}, {%4,%5,%6,%7}, {%8,%9}, {%0,%1,%2,%3};"
                 : "+f"(d[0]), "+f"(d[1]), "+f"(d[2]), "+f"(d[3])
                 : "r"(a0), "r"(a1), "r"(a2), "r"(a3), "r"(b0), "r"(b1));
}
__device__ __forceinline__ void cpa8(uint32_t smem, const void* g) {
    asm volatile("cp.async.ca.shared.global [%0], [%1], 8;" :: "r"(smem), "l"(g));
}
__device__ __forceinline__ void cpa16(uint32_t smem, const void* g) {
    asm volatile("cp.async.cg.shared.global [%0], [%1], 16;" :: "r"(smem), "l"(g));
}
#define CP_COMMIT() asm volatile("cp.async.commit_group;")
#define CP_WAIT0()  asm volatile("cp.async.wait_group 0;")

// ============ launch 0: folds (block 0) + W1hT transpose (blocks 1..8) =====
__global__ void k_fold(const float* __restrict__ W1s, const float* __restrict__ W1d,
                       const float* __restrict__ att1s, const float* __restrict__ att1d,
                       const float* __restrict__ W2s, const float* __restrict__ W2d,
                       const float* __restrict__ att2s, const float* __restrict__ att2d,
                       const float* __restrict__ gamma, const float* __restrict__ beta,
                       const float* __restrict__ rmean, const float* __restrict__ rvar) {
    int t = threadIdx.x;  // 512
    if (blockIdx.x == 0) {
        {   // V1 fold
            int k = t >> 2, h = t & 3;
            float s = 0.f, d = 0.f;
            for (int c = 0; c < HID; c++) {
                s += W1s[k * HD + h * HID + c] * att1s[h * HID + c];
                d += W1d[k * HD + h * HID + c] * att1d[h * HID + c];
            }
            g_V1s[t] = s;  // layout [k*4+h]
            g_V1d[t] = d;
        }
        if (t < HD) {
            float s = 0.f, d = 0.f;
            for (int c = 0; c < OUT_DIM; c++) {
                s += W2s[t * OUT_DIM + c] * att2s[c];
                d += W2d[t * OUT_DIM + c] * att2d[c];
            }
            g_V2s[t] = s;
            g_V2d[t] = d;
            float sc = gamma[t] * rsqrtf(rvar[t] + BN_EPS);
            g_bnsc[t] = sc;
            g_bnsh[t] = beta[t] - rmean[t] * sc;
        }
        return;
    }
    // W1hT transpose: 8 blocks, each thread emits one 16B row-chunk
    int i = (blockIdx.x - 1) * 512 + t;   // [0, 4096)
    int e0 = i * 8;
    int n = e0 >> 7;
    int k = e0 & 127;
    __half tmp[8];
    #pragma unroll
    for (int j = 0; j < 8; j++)
        tmp[j] = __float2half(W1s[(k + j) * HD + n]);
    *(uint4*)(g_W1hT + n * IN_DIM + k) = *(uint4*)tmp;
}

// ============ a1 fold-butterfly helper ======================================
__device__ __forceinline__ void a1_fold_store(const float* vals, int row, bool dual,
                                              int lane, bool b16, bool b8, bool b4) {
    float k4[4];
    #pragma unroll
    for (int i = 0; i < 4; i++) {
        float send = b16 ? vals[i] : vals[4 + i];
        float got = __shfl_xor_sync(0xFFFFFFFFu, send, 16);
        k4[i] = (b16 ? vals[4 + i] : vals[i]) + got;
    }
    float k2[2];
    #pragma unroll
    for (int i = 0; i < 2; i++) {
        float send = b8 ? k4[i] : k4[2 + i];
        float got = __shfl_xor_sync(0xFFFFFFFFu, send, 8);
        k2[i] = (b8 ? k4[2 + i] : k4[i]) + got;
    }
    float send = b4 ? k2[0] : k2[1];
    float got = __shfl_xor_sync(0xFFFFFFFFu, send, 4);
    float k1 = (b4 ? k2[1] : k2[0]) + got;
    k1 += __shfl_xor_sync(0xFFFFFFFFu, k1, 2);
    k1 += __shfl_xor_sync(0xFFFFFFFFu, k1, 1);
    if ((lane & 3) == 0) {
        int o = (lane >> 2) & 3;
        if (lane < 16) g_a1s[row * 4 + o] = k1;
        else if (dual) g_a1d[row * 4 + o] = k1;
    }
}

// ============ launch 1: a1 (blocks 0..1023) + histogram (blocks 1024..4095) =
#define A1_ROWS 32
__global__ void __launch_bounds__(256) k_a1_hist(const float* __restrict__ x,
                                                 const int* __restrict__ dst1,
                                                 const int* __restrict__ dst2) {
    int t = threadIdx.x;
    if (blockIdx.x >= 1024) {
        int e = (blockIdx.x - 1024) * 256 + t;
        if (e < E1) atomicAdd(&g_cnt1[dst1[e]], 1);
        else atomicAdd(&g_cnt2[dst2[e - E1]], 1);
        return;
    }
    int lane = t & 31;
    int warp = (blockIdx.x * 256 + t) >> 5;
    int row0 = warp * A1_ROWS;
    bool dual = row0 < N2;   // warp-uniform (N2 % 32 == 0)
    int k0 = lane * 4;
    float vs[4][4], vd[4][4];
    #pragma unroll
    for (int c = 0; c < 4; c++) {
        float4 v = *(const float4*)&g_V1s[(k0 + c) * 4];
        vs[c][0] = v.x; vs[c][1] = v.y; vs[c][2] = v.z; vs[c][3] = v.w;
        if (dual) {
            float4 w = *(const float4*)&g_V1d[(k0 + c) * 4];
            vd[c][0] = w.x; vd[c][1] = w.y; vd[c][2] = w.z; vd[c][3] = w.w;
        }
    }
    bool b16 = (lane & 16) != 0;
    bool b8  = (lane & 8) != 0;
    bool b4  = (lane & 4) != 0;
    for (int r = 0; r < A1_ROWS; r += 2) {
        int rowA = row0 + r, rowB = rowA + 1;
        float4 xqA = *(const float4*)(x + (size_t)rowA * IN_DIM + lane * 4);
        float4 xqB = *(const float4*)(x + (size_t)rowB * IN_DIM + lane * 4);
        {
            __half2 h0 = __floats2half2_rn(xqA.x, xqA.y);
            __half2 h1 = __floats2half2_rn(xqA.z, xqA.w);
            uint2 pk;
            pk.x = *(unsigned*)&h0;
            pk.y = *(unsigned*)&h1;
            *(uint2*)(g_xh + (size_t)rowA * IN_DIM + lane * 4) = pk;
            __half2 g0 = __floats2half2_rn(xqB.x, xqB.y);
            __half2 g1 = __floats2half2_rn(xqB.z, xqB.w);
            uint2 pk2;
            pk2.x = *(unsigned*)&g0;
            pk2.y = *(unsigned*)&g1;
            *(uint2*)(g_xh + (size_t)rowB * IN_DIM + lane * 4) = pk2;
        }
        float valsA[8] = {0.f, 0.f, 0.f, 0.f, 0.f, 0.f, 0.f, 0.f};
        float valsB[8] = {0.f, 0.f, 0.f, 0.f, 0.f, 0.f, 0.f, 0.f};
        float xaA[4] = {xqA.x, xqA.y, xqA.z, xqA.w};
        float xaB[4] = {xqB.x, xqB.y, xqB.z, xqB.w};
        #pragma unroll
        for (int c = 0; c < 4; c++) {
            valsA[0] = fmaf(xaA[c], vs[c][0], valsA[0]);
            valsA[1] = fmaf(xaA[c], vs[c][1], valsA[1]);
            valsA[2] = fmaf(xaA[c], vs[c][2], valsA[2]);
            valsA[3] = fmaf(xaA[c], vs[c][3], valsA[3]);
            valsB[0] = fmaf(xaB[c], vs[c][0], valsB[0]);
            valsB[1] = fmaf(xaB[c], vs[c][1], valsB[1]);
            valsB[2] = fmaf(xaB[c], vs[c][2], valsB[2]);
            valsB[3] = fmaf(xaB[c], vs[c][3], valsB[3]);
        }
        if (dual) {
            #pragma unroll
            for (int c = 0; c < 4; c++) {
                valsA[4] = fmaf(xaA[c], vd[c][0], valsA[4]);
                valsA[5] = fmaf(xaA[c], vd[c][1], valsA[5]);
                valsA[6] = fmaf(xaA[c], vd[c][2], valsA[6]);
                valsA[7] = fmaf(xaA[c], vd[c][3], valsA[7]);
                valsB[4] = fmaf(xaB[c], vd[c][0], valsB[4]);
                valsB[5] = fmaf(xaB[c], vd[c][1], valsB[5]);
                valsB[6] = fmaf(xaB[c], vd[c][2], valsB[6]);
                valsB[7] = fmaf(xaB[c], vd[c][3], valsB[7]);
            }
        }
        a1_fold_store(valsA, rowA, dual, lane, b16, b8, b4);
        a1_fold_store(valsB, rowB, dual, lane, b16, b8, b4);
    }
}

// ============ launch 2: scans (2 blocks) ====================================
__global__ void k1_scan() {
    int t = threadIdx.x;  // 512
    const int* cnt = blockIdx.x == 0 ? g_cnt1 : g_cnt2;
    int* rs  = blockIdx.x == 0 ? g_rs1  : g_rs2;
    int* cur = blockIdx.x == 0 ? g_cur1 : g_cur2;
    int n = blockIdx.x == 0 ? N2 : N3;
    int per = n >> 9;
    __shared__ int part[512];
    int base = t * per;
    int s = 0;
    for (int i = 0; i < per; i += 4) {
        int4 c4 = *(const int4*)&cnt[base + i];
        s += c4.x + c4.y + c4.z + c4.w;
    }
    part[t] = s;
    __syncthreads();
    for (int off = 1; off < 512; off <<= 1) {
        int v = (t >= off) ? part[t - off] : 0;
        __syncthreads();
        part[t] += v;
        __syncthreads();
    }
    int run = (t == 0) ? 0 : part[t - 1];
    for (int i = 0; i < per; i += 4) {
        int4 c4 = *(const int4*)&cnt[base + i];
        int4 r4;
        r4.x = run;
        r4.y = run + c4.x;
        r4.z = r4.y + c4.y;
        r4.w = r4.z + c4.z;
        run = r4.w + c4.w;
        *(int4*)&rs[base + i] = r4;
        *(int4*)&cur[base + i] = r4;
    }
    if (t == 511) rs[n] = run;
}

// ============ launch 3: scatter + per-edge p + re-zero counts [ncu capture] =
__global__ void k2_scatter_zero(const int* __restrict__ src1, const int* __restrict__ dst1,
                                const int* __restrict__ src2, const int* __restrict__ dst2) {
    int t = threadIdx.x;  // 512
    if (blockIdx.x < 1536) {
        int e = blockIdx.x * 512 + t;
        if (e < E1) {
            int s = src1[e], d = dst1[e];
            int pos = atomicAdd(&g_cur1[d], 1);
            g_srcs1[pos] = s;
            float4 asv = *(const float4*)&g_a1s[s * 4];
            float4 adv = *(const float4*)&g_a1d[d * 4];
            float e0 = asv.x + adv.x, e1 = asv.y + adv.y;
            float e2 = asv.z + adv.z, e3 = asv.w + adv.w;
            e0 = e0 > 0.f ? e0 : NEG_SLOPE * e0;
            e1 = e1 > 0.f ? e1 : NEG_SLOPE * e1;
            e2 = e2 > 0.f ? e2 : NEG_SLOPE * e2;
            e3 = e3 > 0.f ? e3 : NEG_SLOPE * e3;
            g_p1[pos] = make_float4(__expf(e0), __expf(e1), __expf(e2), __expf(e3));
        } else {
            int ee = e - E1;
            int pos = atomicAdd(&g_cur2[dst2[ee]], 1);
            g_srcs2[pos] = src2[ee];
        }
        return;
    }
    int z = (blockIdx.x - 1536) * 512 + t;
    if (z < N2) g_cnt1[z] = 0;
    else if (z - N2 < N3) g_cnt2[z - N2] = 0;
}

// ============ launch 4: layer-1 aggregate, cp.async staged (warp per dst) ==
#define M1_WARPS 8
#define M1_WBYTES (4096 + 256 + 64)
__global__ void __launch_bounds__(256) k_msg1() {
    extern __shared__ __align__(16) char sm1[];
    int t = threadIdx.x, lane = t & 31, wl = t >> 5;
    char* wbase = sm1 + wl * M1_WBYTES;
    __half* buf = (__half*)wbase;                 // [16 edges][128 halves]
    float4* pbuf = (float4*)(wbase + 4096);       // [16]
    int*    sbuf = (int*)(wbase + 4096 + 256);    // [16]
    int w = blockIdx.x * M1_WARPS + wl;
    if (w >= N2) return;
    int start = g_rs1[w], end = g_rs1[w + 1];
    __half* outp = g_agg1h + (size_t)w * (HEADS * IN_DIM);
    if (start == end) {
        uint4 z = make_uint4(0u, 0u, 0u, 0u);
        *(uint4*)(outp + lane * 16) = z;   // 32 x 16 halves = 512
        return;
    }
    float den[4] = {0.f, 0.f, 0.f, 0.f};
    float acc[4][4];
    #pragma unroll
    for (int h = 0; h < 4; h++)
        #pragma unroll
        for (int c = 0; c < 4; c++) acc[h][c] = 0.f;

    for (int base = start; base < end; base += 16) {
        int n = min(16, end - base);
        if (lane < n) {
            int s = g_srcs1[base + lane];
            float4 pv = g_p1[base + lane];
            sbuf[lane] = s;
            pbuf[lane] = pv;
            den[0] += pv.x; den[1] += pv.y; den[2] += pv.z; den[3] += pv.w;
        }
        __syncwarp();
        for (int j = 0; j < n; j++) {
            int s = sbuf[j];
            cpa8((uint32_t)__cvta_generic_to_shared(buf + j * 128 + lane * 4),
                 g_xh + (size_t)s * IN_DIM + lane * 4);
        }
        CP_COMMIT();
        CP_WAIT0();
        __syncwarp();
        for (int j = 0; j < n; j++) {
            float4 pv = pbuf[j];     // LDS broadcast
            uint2 v = *(const uint2*)(buf + j * 128 + lane * 4);
            float2 f01 = __half22float2(*(__half2*)&v.x);
            float2 f23 = __half22float2(*(__half2*)&v.y);
            acc[0][0] = fmaf(pv.x, f01.x, acc[0][0]);
            acc[0][1] = fmaf(pv.x, f01.y, acc[0][1]);
            acc[0][2] = fmaf(pv.x, f23.x, acc[0][2]);
            acc[0][3] = fmaf(pv.x, f23.y, acc[0][3]);
            acc[1][0] = fmaf(pv.y, f01.x, acc[1][0]);
            acc[1][1] = fmaf(pv.y, f01.y, acc[1][1]);
            acc[1][2] = fmaf(pv.y, f23.x, acc[1][2]);
            acc[1][3] = fmaf(pv.y, f23.y, acc[1][3]);
            acc[2][0] = fmaf(pv.z, f01.x, acc[2][0]);
            acc[2][1] = fmaf(pv.z, f01.y, acc[2][1]);
            acc[2][2] = fmaf(pv.z, f23.x, acc[2][2]);
            acc[2][3] = fmaf(pv.z, f23.y, acc[2][3]);
            acc[3][0] = fmaf(pv.w, f01.x, acc[3][0]);
            acc[3][1] = fmaf(pv.w, f01.y, acc[3][1]);
            acc[3][2] = fmaf(pv.w, f23.x, acc[3][2]);
            acc[3][3] = fmaf(pv.w, f23.y, acc[3][3]);
        }
        __syncwarp();
    }
    #pragma unroll
    for (int h = 0; h < 4; h++) {
        float inv = 1.0f / fmaxf(wredsum(den[h]), 1e-16f);
        __half2 q0 = __floats2half2_rn(acc[h][0] * inv, acc[h][1] * inv);
        __half2 q1 = __floats2half2_rn(acc[h][2] * inv, acc[h][3] * inv);
        uint2 pkt;
        pkt.x = *(unsigned*)&q0;
        pkt.y = *(unsigned*)&q1;
        *(uint2*)(outp + h * IN_DIM + lane * 4) = pkt;
    }
}

// ============ launch 5: layer-1 HMMA GEMM + BN + ELU + fp16 store + a2 ======
__global__ void __launch_bounds__(256) k_out1(const float* __restrict__ b1) {
    __shared__ __align__(16) __half As[128 * 128];
    __shared__ __align__(16) __half Bs[64 * 128];
    int t = threadIdx.x;
    int d0 = blockIdx.x * 128;
    int head = blockIdx.y;

    {
        #pragma unroll
        for (int j = 0; j < 8; j++) {
            int i = j * 256 + t;
            int row = i >> 4, c = i & 15;
            uint4 v = *(const uint4*)(g_agg1h + (size_t)(d0 + row) * 512
                                      + head * IN_DIM + c * 8);
            *(uint4*)((char*)As + row * 256 + ((c ^ (row & 7)) << 4)) = v;
        }
        #pragma unroll
        for (int j = 0; j < 4; j++) {
            int i = j * 256 + t;
            int n = i >> 4, c = i & 15;
            uint4 v = *(const uint4*)(g_W1hT + (head * 64 + n) * IN_DIM + c * 8);
            *(uint4*)((char*)Bs + n * 256 + ((c ^ (n & 7)) << 4)) = v;
        }
    }
    __syncthreads();

    int lane = t & 31;
    int warp = t >> 5;
    int R = warp * 16;
    uint32_t as_base = (uint32_t)__cvta_generic_to_shared(As);
    uint32_t bs_base = (uint32_t)__cvta_generic_to_shared(Bs);

    float acc[8][4];
    #pragma unroll
    for (int nt = 0; nt < 8; nt++)
        #pragma unroll
        for (int c = 0; c < 4; c++) acc[nt][c] = 0.f;

    int grp = lane >> 3, rowin = lane & 7;
    #pragma unroll
    for (int ks = 0; ks < 8; ks++) {
        int kc = ks * 2;
        uint32_t a0, a1, a2, a3;
        {
            int row = R + rowin + ((grp & 1) << 3);
            int chunk = (kc + ((grp >> 1) & 1)) ^ (row & 7);
            ldsm_x4(a0, a1, a2, a3, as_base + row * 256 + (chunk << 4));
        }
        #pragma unroll
        for (int np = 0; np < 4; np++) {
            uint32_t b0, b1v, b2, b3;
            int n = np * 16 + rowin + ((grp >> 1) << 3);
            int chunk = (kc + (grp & 1)) ^ (n & 7);
            ldsm_x4(b0, b1v, b2, b3, bs_base + n * 256 + (chunk << 4));
            mma16816(acc[np * 2], a0, a1, a2, a3, b0, b1v);
            mma16816(acc[np * 2 + 1], a0, a1, a2, a3, b2, b3);
        }
    }

    int q = lane >> 2;
    int cpair = (lane & 3) * 2;
    int row_lo = d0 + R + q;
    int row_hi = row_lo + 8;
    float ps_lo = 0.f, pd_lo = 0.f, ps_hi = 0.f, pd_hi = 0.f;
    #pragma unroll
    for (int nt = 0; nt < 8; nt++) {
        int gc = head * 64 + nt * 8 + cpair;
        float2 bb = *(const float2*)&b1[gc];
        float2 sc = *(const float2*)&g_bnsc[gc];
        float2 sh = *(const float2*)&g_bnsh[gc];
        float2 vs = *(const float2*)&g_V2s[gc];
        float2 vd = *(const float2*)&g_V2d[gc];
        float v0 = (acc[nt][0] + bb.x) * sc.x + sh.x;
        float v1 = (acc[nt][1] + bb.y) * sc.y + sh.y;
        float v2 = (acc[nt][2] + bb.x) * sc.x + sh.x;
        float v3 = (acc[nt][3] + bb.y) * sc.y + sh.y;
        v0 = v0 > 0.f ? v0 : __expf(v0) - 1.f;
        v1 = v1 > 0.f ? v1 : __expf(v1) - 1.f;
        v2 = v2 > 0.f ? v2 : __expf(v2) - 1.f;
        v3 = v3 > 0.f ? v3 : __expf(v3) - 1.f;
        ps_lo = fmaf(v0, vs.x, fmaf(v1, vs.y, ps_lo));
        pd_lo = fmaf(v0, vd.x, fmaf(v1, vd.y, pd_lo));
        ps_hi = fmaf(v2, vs.x, fmaf(v3, vs.y, ps_hi));
        pd_hi = fmaf(v2, vd.x, fmaf(v3, vd.y, pd_hi));
        __half2 lo = __floats2half2_rn(v0, v1);
        __half2 hi = __floats2half2_rn(v2, v3);
        *(__half2*)(g_h1h + (size_t)row_lo * HD + gc) = lo;
        *(__half2*)(g_h1h + (size_t)row_hi * HD + gc) = hi;
    }
    #pragma unroll
    for (int m = 1; m < 4; m <<= 1) {
        ps_lo += __shfl_xor_sync(0xFFFFFFFFu, ps_lo, m);
        pd_lo += __shfl_xor_sync(0xFFFFFFFFu, pd_lo, m);
        ps_hi += __shfl_xor_sync(0xFFFFFFFFu, ps_hi, m);
        pd_hi += __shfl_xor_sync(0xFFFFFFFFu, pd_hi, m);
    }
    if ((lane & 3) == 0) {
        g_a2sp[row_lo * 4 + head] = ps_lo;
        g_a2sp[row_hi * 4 + head] = ps_hi;
        if (row_lo < N3) g_a2dp[row_lo * 4 + head] = pd_lo;
        if (row_hi < N3) g_a2dp[row_hi * 4 + head] = pd_hi;
    }
}

// ============ launch 6: layer-2 aggregate, cp.async staged (warp per dst) ==
#define M2_WARPS 8
#define M2_WBYTES (4096 + 32 + 32)
__global__ void __launch_bounds__(256) k_msg2() {
    extern __shared__ __align__(16) char sm2[];
    int t = threadIdx.x, lane = t & 31, wl = t >> 5;
    char* wbase = sm2 + wl * M2_WBYTES;
    __half* buf = (__half*)wbase;                // [8 edges][256 halves]
    float* pbuf = (float*)(wbase + 4096);        // [8]
    int*   sbuf = (int*)(wbase + 4096 + 32);     // [8]
    int w = blockIdx.x * M2_WARPS + wl;
    if (w >= N3) return;
    int start = g_rs2[w], end = g_rs2[w + 1];
    float* outp = g_agg2 + (size_t)w * HD;
    if (start == end) {
        float4 z = make_float4(0.f, 0.f, 0.f, 0.f);
        *(float4*)(outp + lane * 8) = z;
        *(float4*)(outp + lane * 8 + 4) = z;
        return;
    }
    float4 adv = *(const float4*)&g_a2dp[w * 4];
    float ad = adv.x + adv.y + adv.z + adv.w;
    float den = 0.f;
    float acc[8];
    #pragma unroll
    for (int f = 0; f < 8; f++) acc[f] = 0.f;

    for (int base = start; base < end; base += 8) {
        int n = min(8, end - base);
        if (lane < n) {
            int s = g_srcs2[base + lane];
            float4 sv = *(const float4*)&g_a2sp[s * 4];
            float e = sv.x + sv.y + sv.z + sv.w + ad;
            e = e > 0.f ? e : NEG_SLOPE * e;
            float p = __expf(e);
            sbuf[lane] = s;
            pbuf[lane] = p;
            den += p;
        }
        __syncwarp();
        for (int j = 0; j < n; j++) {
            int s = sbuf[j];
            cpa16((uint32_t)__cvta_generic_to_shared(buf + j * 256 + lane * 8),
                  g_h1h + (size_t)s * HD + lane * 8);
        }
        CP_COMMIT();
        CP_WAIT0();
        __syncwarp();
        for (int j = 0; j < n; j++) {
            float a = pbuf[j];
            uint4 v = *(const uint4*)(buf + j * 256 + lane * 8);
            float2 f0 = __half22float2(*(__half2*)&v.x);
            float2 f1 = __half22float2(*(__half2*)&v.y);
            float2 f2 = __half22float2(*(__half2*)&v.z);
            float2 f3 = __half22float2(*(__half2*)&v.w);
            acc[0] = fmaf(a, f0.x, acc[0]);
            acc[1] = fmaf(a, f0.y, acc[1]);
            acc[2] = fmaf(a, f1.x, acc[2]);
            acc[3] = fmaf(a, f1.y, acc[3]);
            acc[4] = fmaf(a, f2.x, acc[4]);
            acc[5] = fmaf(a, f2.y, acc[5]);
            acc[6] = fmaf(a, f3.x, acc[6]);
            acc[7] = fmaf(a, f3.y, acc[7]);
        }
        __syncwarp();
    }
    float inv = 1.0f / fmaxf(wredsum(den), 1e-16f);
    *(float4*)(outp + lane * 8) =
        make_float4(acc[0] * inv, acc[1] * inv, acc[2] * inv, acc[3] * inv);
    *(float4*)(outp + lane * 8 + 4) =
        make_float4(acc[4] * inv, acc[5] * inv, acc[6] * inv, acc[7] * inv);
}

// ============ launch 7: layer-2 output GEMM + b2 ============================
#define G2_ROWS 64
__global__ void k_out2(const float* __restrict__ W2s, const float* __restrict__ b2,
                       float* __restrict__ out) {
    extern __shared__ float sm[];
    float* Ws = sm;
    float* Ag = sm + HD * OUT_DIM;
    int t = threadIdx.x;  // 256
    for (int i = t; i < HD * OUT_DIM / 4; i += 256)
        ((float4*)Ws)[i] = ((const float4*)W2s)[i];
    int d0 = blockIdx.x * G2_ROWS;
    const float4* agg_src = (const float4*)(g_agg2 + (size_t)d0 * HD);
    for (int i = t; i < G2_ROWS * HD / 4; i += 256)
        ((float4*)Ag)[i] = agg_src[i];
    __syncthreads();

    int cg = (t & 15) * 4;
    int r0 = (t >> 4) * 4;
    float acc[4][4];
    #pragma unroll
    for (int r = 0; r < 4; r++)
        #pragma unroll
        for (int c = 0; c < 4; c++) acc[r][c] = 0.f;

    #pragma unroll 4
    for (int k = 0; k < HD; k++) {
        float4 wv = *(float4*)&Ws[k * OUT_DIM + cg];
        #pragma unroll
        for (int r = 0; r < 4; r++) {
            float a = Ag[(r0 + r) * HD + k];
            acc[r][0] = fmaf(a, wv.x, acc[r][0]);
            acc[r][1] = fmaf(a, wv.y, acc[r][1]);
            acc[r][2] = fmaf(a, wv.z, acc[r][2]);
            acc[r][3] = fmaf(a, wv.w, acc[r][3]);
        }
    }
    float4 bv = *(const float4*)&b2[cg];
    #pragma unroll
    for (int r = 0; r < 4; r++) {
        int d = d0 + r0 + r;
        float4 o = make_float4(acc[r][0] + bv.x, acc[r][1] + bv.y,
                               acc[r][2] + bv.z, acc[r][3] + bv.w);
        *(float4*)&out[(size_t)d * OUT_DIM + cg] = o;
    }
}

// ---------------- launch ----------------
extern "C" void kernel_launch(void* const* d_in, const int* in_sizes, int n_in,
                              void* d_out, int out_size) {
    const float* x     = (const float*)d_in[0];
    const float* W1s   = (const float*)d_in[1];
    const float* W1d   = (const float*)d_in[2];
    const float* att1s = (const float*)d_in[3];
    const float* att1d = (const float*)d_in[4];
    const float* b1    = (const float*)d_in[5];
    const float* gamma = (const float*)d_in[6];
    const float* beta  = (const float*)d_in[7];
    const float* rmean = (const float*)d_in[8];
    const float* rvar  = (const float*)d_in[9];
    const float* W2s   = (const float*)d_in[10];
    const float* W2d   = (const float*)d_in[11];
    const float* att2s = (const float*)d_in[12];
    const float* att2d = (const float*)d_in[13];
    const float* b2    = (const float*)d_in[14];
    const int* src1    = (const int*)d_in[15];
    const int* dst1    = (const int*)d_in[16];
    const int* src2    = (const int*)d_in[17];
    const int* dst2    = (const int*)d_in[18];
    float* out = (float*)d_out;

    cudaFuncSetAttribute(k_msg1, cudaFuncAttributeMaxDynamicSharedMemorySize,
                         M1_WARPS * M1_WBYTES);
    cudaFuncSetAttribute(k_msg2, cudaFuncAttributeMaxDynamicSharedMemorySize,
                         M2_WARPS * M2_WBYTES);
    cudaFuncSetAttribute(k_out2, cudaFuncAttributeMaxDynamicSharedMemorySize,
                         (HD * OUT_DIM + G2_ROWS * HD) * 4);

    // 0: folds + W1hT transpose (tiny)
    k_fold<<<9, 512>>>(W1s, W1d, att1s, att1d, W2s, W2d, att2s, att2d,
                       gamma, beta, rmean, rvar);
    // 1: a1 (blocks 0..1023) overlapped with histogram (blocks 1024..4095)
    k_a1_hist<<<1024 + (E1 + E2) / 256, 256>>>(x, dst1, dst2);
    // 2: scans (both layers)
    k1_scan<<<2, 512>>>();
    // 3: scatter + per-edge p + re-zero counters (ncu capture index 3)
    k2_scatter_zero<<<1536 + (N2 + N3) / 512, 512>>>(src1, dst1, src2, dst2);
    // 4: msg1
    k_msg1<<<N2 / M1_WARPS, 256, M1_WARPS * M1_WBYTES>>>();
    // 5: out1 (HMMA)
    k_out1<<<dim3(N2 / 128, HEADS), 256>>>(b1);
    // 6: msg2
    k_msg2<<<N3 / M2_WARPS, 256, M2_WARPS * M2_WBYTES>>>();
    // 7: out2
    k_out2<<<N3 / G2_ROWS, 256, (HD * OUT_DIM + G2_ROWS * HD) * 4>>>(W2s, b2, out);
}

// round 15
// speedup vs baseline: 1.2031x; 1.2031x over previous
#include <cuda_runtime.h>
#include <cuda_fp16.h>
#include <math.h>
#include <stddef.h>
#include <stdint.h>

#define N1 262144
#define N2 65536
#define N3 16384
#define E1 524288
#define E2 262144
#define IN_DIM 128
#define HID 64
#define HEADS 4
#define HD 256
#define OUT_DIM 64
#define NEG_SLOPE 0.2f
#define BN_EPS 1e-5f

// ---------------- scratch (device globals: zero-initialized at load) -------
__device__ __align__(16) float  g_V1s[IN_DIM * HEADS];   // [k][h]
__device__ __align__(16) float  g_V1d[IN_DIM * HEADS];
__device__ __align__(16) float  g_V2s[HD];
__device__ __align__(16) float  g_V2d[HD];
__device__ __align__(16) float  g_bnsc[HD];
__device__ __align__(16) float  g_bnsh[HD];
__device__ __align__(16) __half g_W1hT[HD * IN_DIM];     // [n][k] fp16 W1_src^T

__device__ __align__(16) float  g_a1s[N1 * HEADS];
__device__ __align__(16) float  g_a1d[N2 * HEADS];
__device__ __align__(16) __half g_xh[(size_t)N1 * IN_DIM];            // 67 MB
__device__ __align__(16) __half g_agg1h[(size_t)N2 * HEADS * IN_DIM]; // 67 MB
__device__ __align__(16) __half g_h1h[(size_t)N2 * HD];               // 33 MB

__device__ __align__(16) float g_a2sp[N2 * HEADS];   // [row*4+head]
__device__ __align__(16) float g_a2dp[N3 * HEADS];   // [row*4+head]
__device__ __align__(16) float g_agg2[(size_t)N3 * HD];               // 16 MB

// CSR-by-dst scratch (zero-init counts; re-zeroed per run inside scatter)
__device__ __align__(16) int    g_cnt1[N2];
__device__ __align__(16) int    g_rs1[N2 + 4];
__device__ __align__(16) int    g_cur1[N2];
__device__ __align__(16) int    g_srcs1[E1];
__device__ __align__(16) float4 g_p1[E1];            // per-edge softmax numerators
__device__ __align__(16) int    g_cnt2[N3];
__device__ __align__(16) int    g_rs2[N3 + 4];
__device__ __align__(16) int    g_cur2[N3];
__device__ __align__(16) int    g_srcs2[E2];

// ---------------- helpers ----------------
__device__ __forceinline__ float wredsum(float v) {
    #pragma unroll
    for (int o = 16; o; o >>= 1) v += __shfl_xor_sync(0xFFFFFFFFu, v, o);
    return v;
}
__device__ __forceinline__ void ldsm_x4(uint32_t& r0, uint32_t& r1, uint32_t& r2,
                                        uint32_t& r3, uint32_t addr) {
    asm volatile("ldmatrix.sync.aligned.m8n8.x4.shared.b16 {%0,%1,%2,%3}, [%4];"
                 : "=r"(r0), "=r"(r1), "=r"(r2), "=r"(r3) : "r"(addr));
}
__device__ __forceinline__ void mma16816(float* d, uint32_t a0, uint32_t a1,
                                         uint32_t a2, uint32_t a3,
                                         uint32_t b0, uint32_t b1) {
    asm volatile("mma.sync.aligned.m16n8k16.row.col.f32.f16.f16.f32 "
                 "{%0,%1,%2,%3}, {%4,%5,%6,%7}, {%8,%9}, {%0,%1,%2,%3};"
                 : "+f"(d[0]), "+f"(d[1]), "+f"(d[2]), "+f"(d[3])
                 : "r"(a0), "r"(a1), "r"(a2), "r"(a3), "r"(b0), "r"(b1));
}
__device__ __forceinline__ void cpa8(uint32_t smem, const void* g) {
    asm volatile("cp.async.ca.shared.global [%0], [%1], 8;" :: "r"(smem), "l"(g));
}
__device__ __forceinline__ void cpa16(uint32_t smem, const void* g) {
    asm volatile("cp.async.cg.shared.global [%0], [%1], 16;" :: "r"(smem), "l"(g));
}
#define CP_COMMIT() asm volatile("cp.async.commit_group;")
#define CP_WAIT0()  asm volatile("cp.async.wait_group 0;")

// ============ launch 0: hist (0..1535) + fold (1536) + W1hT transpose (1537..1544)
__global__ void k0_hist_fold(const int* __restrict__ dst1, const int* __restrict__ dst2,
                             const float* __restrict__ W1s, const float* __restrict__ W1d,
                             const float* __restrict__ att1s, const float* __restrict__ att1d,
                             const float* __restrict__ W2s, const float* __restrict__ W2d,
                             const float* __restrict__ att2s, const float* __restrict__ att2d,
                             const float* __restrict__ gamma, const float* __restrict__ beta,
                             const float* __restrict__ rmean, const float* __restrict__ rvar) {
    int t = threadIdx.x;  // 512
    if (blockIdx.x < 1536) {
        int e = blockIdx.x * 512 + t;
        if (e < E1) atomicAdd(&g_cnt1[dst1[e]], 1);
        else atomicAdd(&g_cnt2[dst2[e - E1]], 1);
        return;
    }
    if (blockIdx.x == 1536) {
        {   // V1 fold
            int k = t >> 2, h = t & 3;
            float s = 0.f, d = 0.f;
            for (int c = 0; c < HID; c++) {
                s += W1s[k * HD + h * HID + c] * att1s[h * HID + c];
                d += W1d[k * HD + h * HID + c] * att1d[h * HID + c];
            }
            g_V1s[t] = s;  // layout [k*4+h]
            g_V1d[t] = d;
        }
        if (t < HD) {
            float s = 0.f, d = 0.f;
            for (int c = 0; c < OUT_DIM; c++) {
                s += W2s[t * OUT_DIM + c] * att2s[c];
                d += W2d[t * OUT_DIM + c] * att2d[c];
            }
            g_V2s[t] = s;
            g_V2d[t] = d;
            float sc = gamma[t] * rsqrtf(rvar[t] + BN_EPS);
            g_bnsc[t] = sc;
            g_bnsh[t] = beta[t] - rmean[t] * sc;
        }
        return;
    }
    // W1hT transpose spread over 8 blocks
    {
        int i = (blockIdx.x - 1537) * 512 + t;   // [0, 4096)
        int e0 = i * 8;
        int n = e0 >> 7;
        int k = e0 & 127;
        __half tmp[8];
        #pragma unroll
        for (int j = 0; j < 8; j++)
            tmp[j] = __float2half(W1s[(k + j) * HD + n]);
        *(uint4*)(g_W1hT + n * IN_DIM + k) = *(uint4*)tmp;
    }
}

// ============ a1 fold-butterfly helper ======================================
__device__ __forceinline__ void a1_fold_store(const float* vals, int row, bool dual,
                                              int lane, bool b16, bool b8, bool b4) {
    float k4[4];
    #pragma unroll
    for (int i = 0; i < 4; i++) {
        float send = b16 ? vals[i] : vals[4 + i];
        float got = __shfl_xor_sync(0xFFFFFFFFu, send, 16);
        k4[i] = (b16 ? vals[4 + i] : vals[i]) + got;
    }
    float k2[2];
    #pragma unroll
    for (int i = 0; i < 2; i++) {
        float send = b8 ? k4[i] : k4[2 + i];
        float got = __shfl_xor_sync(0xFFFFFFFFu, send, 8);
        k2[i] = (b8 ? k4[2 + i] : k4[i]) + got;
    }
    float send = b4 ? k2[0] : k2[1];
    float got = __shfl_xor_sync(0xFFFFFFFFu, send, 4);
    float k1 = (b4 ? k2[1] : k2[0]) + got;
    k1 += __shfl_xor_sync(0xFFFFFFFFu, k1, 2);
    k1 += __shfl_xor_sync(0xFFFFFFFFu, k1, 1);
    if ((lane & 3) == 0) {
        int o = (lane >> 2) & 3;
        if (lane < 16) g_a1s[row * 4 + o] = k1;
        else if (dual) g_a1d[row * 4 + o] = k1;
    }
}

// ============ launch 1: scans (blocks 0,1) + a1 (blocks 2..513, 512 thr) ====
#define A1_ROWS 32
__global__ void __launch_bounds__(512) k_scan_a1(const float* __restrict__ x) {
    int t = threadIdx.x;  // 512
    if (blockIdx.x < 2) {
        const int* cnt = blockIdx.x == 0 ? g_cnt1 : g_cnt2;
        int* rs  = blockIdx.x == 0 ? g_rs1  : g_rs2;
        int* cur = blockIdx.x == 0 ? g_cur1 : g_cur2;
        int n = blockIdx.x == 0 ? N2 : N3;
        int per = n >> 9;
        __shared__ int part[512];
        int base = t * per;
        int s = 0;
        for (int i = 0; i < per; i += 4) {
            int4 c4 = *(const int4*)&cnt[base + i];
            s += c4.x + c4.y + c4.z + c4.w;
        }
        part[t] = s;
        __syncthreads();
        for (int off = 1; off < 512; off <<= 1) {
            int v = (t >= off) ? part[t - off] : 0;
            __syncthreads();
            part[t] += v;
            __syncthreads();
        }
        int run = (t == 0) ? 0 : part[t - 1];
        for (int i = 0; i < per; i += 4) {
            int4 c4 = *(const int4*)&cnt[base + i];
            int4 r4;
            r4.x = run;
            r4.y = run + c4.x;
            r4.z = r4.y + c4.y;
            r4.w = r4.z + c4.z;
            run = r4.w + c4.w;
            *(int4*)&rs[base + i] = r4;
            *(int4*)&cur[base + i] = r4;
        }
        if (t == 511) rs[n] = run;
        return;
    }
    // a1: warp per 32 rows, V in registers, row pairs for MLP 2
    int lane = t & 31;
    int warp = ((blockIdx.x - 2) * 512 + t) >> 5;
    int row0 = warp * A1_ROWS;
    bool dual = row0 < N2;   // warp-uniform (N2 % 32 == 0)
    int k0 = lane * 4;
    float vs[4][4], vd[4][4];
    #pragma unroll
    for (int c = 0; c < 4; c++) {
        float4 v = *(const float4*)&g_V1s[(k0 + c) * 4];
        vs[c][0] = v.x; vs[c][1] = v.y; vs[c][2] = v.z; vs[c][3] = v.w;
        if (dual) {
            float4 w = *(const float4*)&g_V1d[(k0 + c) * 4];
            vd[c][0] = w.x; vd[c][1] = w.y; vd[c][2] = w.z; vd[c][3] = w.w;
        }
    }
    bool b16 = (lane & 16) != 0;
    bool b8  = (lane & 8) != 0;
    bool b4  = (lane & 4) != 0;
    for (int r = 0; r < A1_ROWS; r += 2) {
        int rowA = row0 + r, rowB = rowA + 1;
        float4 xqA = *(const float4*)(x + (size_t)rowA * IN_DIM + lane * 4);
        float4 xqB = *(const float4*)(x + (size_t)rowB * IN_DIM + lane * 4);
        {
            __half2 h0 = __floats2half2_rn(xqA.x, xqA.y);
            __half2 h1 = __floats2half2_rn(xqA.z, xqA.w);
            uint2 pk;
            pk.x = *(unsigned*)&h0;
            pk.y = *(unsigned*)&h1;
            *(uint2*)(g_xh + (size_t)rowA * IN_DIM + lane * 4) = pk;
            __half2 g0 = __floats2half2_rn(xqB.x, xqB.y);
            __half2 g1 = __floats2half2_rn(xqB.z, xqB.w);
            uint2 pk2;
            pk2.x = *(unsigned*)&g0;
            pk2.y = *(unsigned*)&g1;
            *(uint2*)(g_xh + (size_t)rowB * IN_DIM + lane * 4) = pk2;
        }
        float valsA[8] = {0.f, 0.f, 0.f, 0.f, 0.f, 0.f, 0.f, 0.f};
        float valsB[8] = {0.f, 0.f, 0.f, 0.f, 0.f, 0.f, 0.f, 0.f};
        float xaA[4] = {xqA.x, xqA.y, xqA.z, xqA.w};
        float xaB[4] = {xqB.x, xqB.y, xqB.z, xqB.w};
        #pragma unroll
        for (int c = 0; c < 4; c++) {
            valsA[0] = fmaf(xaA[c], vs[c][0], valsA[0]);
            valsA[1] = fmaf(xaA[c], vs[c][1], valsA[1]);
            valsA[2] = fmaf(xaA[c], vs[c][2], valsA[2]);
            valsA[3] = fmaf(xaA[c], vs[c][3], valsA[3]);
            valsB[0] = fmaf(xaB[c], vs[c][0], valsB[0]);
            valsB[1] = fmaf(xaB[c], vs[c][1], valsB[1]);
            valsB[2] = fmaf(xaB[c], vs[c][2], valsB[2]);
            valsB[3] = fmaf(xaB[c], vs[c][3], valsB[3]);
        }
        if (dual) {
            #pragma unroll
            for (int c = 0; c < 4; c++) {
                valsA[4] = fmaf(xaA[c], vd[c][0], valsA[4]);
                valsA[5] = fmaf(xaA[c], vd[c][1], valsA[5]);
                valsA[6] = fmaf(xaA[c], vd[c][2], valsA[6]);
                valsA[7] = fmaf(xaA[c], vd[c][3], valsA[7]);
                valsB[4] = fmaf(xaB[c], vd[c][0], valsB[4]);
                valsB[5] = fmaf(xaB[c], vd[c][1], valsB[5]);
                valsB[6] = fmaf(xaB[c], vd[c][2], valsB[6]);
                valsB[7] = fmaf(xaB[c], vd[c][3], valsB[7]);
            }
        }
        a1_fold_store(valsA, rowA, dual, lane, b16, b8, b4);
        a1_fold_store(valsB, rowB, dual, lane, b16, b8, b4);
    }
}

// ============ launch 2: scatter + per-edge p + re-zero counts ===============
__global__ void k2_scatter_zero(const int* __restrict__ src1, const int* __restrict__ dst1,
                                const int* __restrict__ src2, const int* __restrict__ dst2) {
    int t = threadIdx.x;  // 512
    if (blockIdx.x < 1536) {
        int e = blockIdx.x * 512 + t;
        if (e < E1) {
            int s = src1[e], d = dst1[e];
            int pos = atomicAdd(&g_cur1[d], 1);
            g_srcs1[pos] = s;
            float4 asv = *(const float4*)&g_a1s[s * 4];
            float4 adv = *(const float4*)&g_a1d[d * 4];
            float e0 = asv.x + adv.x, e1 = asv.y + adv.y;
            float e2 = asv.z + adv.z, e3 = asv.w + adv.w;
            e0 = e0 > 0.f ? e0 : NEG_SLOPE * e0;
            e1 = e1 > 0.f ? e1 : NEG_SLOPE * e1;
            e2 = e2 > 0.f ? e2 : NEG_SLOPE * e2;
            e3 = e3 > 0.f ? e3 : NEG_SLOPE * e3;
            g_p1[pos] = make_float4(__expf(e0), __expf(e1), __expf(e2), __expf(e3));
        } else {
            int ee = e - E1;
            int pos = atomicAdd(&g_cur2[dst2[ee]], 1);
            g_srcs2[pos] = src2[ee];
        }
        return;
    }
    int z = (blockIdx.x - 1536) * 512 + t;
    if (z < N2) g_cnt1[z] = 0;
    else if (z - N2 < N3) g_cnt2[z - N2] = 0;
}

// ============ launch 3: layer-1 aggregate [ncu capture] =====================
#define M1_WARPS 8
#define M1_WBYTES (4096 + 256 + 64)
__global__ void __launch_bounds__(256) k_msg1() {
    extern __shared__ __align__(16) char sm1[];
    int t = threadIdx.x, lane = t & 31, wl = t >> 5;
    char* wbase = sm1 + wl * M1_WBYTES;
    __half* buf = (__half*)wbase;                 // [16 edges][128 halves]
    float4* pbuf = (float4*)(wbase + 4096);       // [16]
    int*    sbuf = (int*)(wbase + 4096 + 256);    // [16]
    int w = blockIdx.x * M1_WARPS + wl;
    if (w >= N2) return;
    int start = g_rs1[w], end = g_rs1[w + 1];
    __half* outp = g_agg1h + (size_t)w * (HEADS * IN_DIM);
    if (start == end) {
        uint4 z = make_uint4(0u, 0u, 0u, 0u);
        *(uint4*)(outp + lane * 16) = z;   // 32 x 16 halves = 512
        return;
    }
    float den[4] = {0.f, 0.f, 0.f, 0.f};
    float acc[4][4];
    #pragma unroll
    for (int h = 0; h < 4; h++)
        #pragma unroll
        for (int c = 0; c < 4; c++) acc[h][c] = 0.f;

    for (int base = start; base < end; base += 16) {
        int n = min(16, end - base);
        if (lane < n) {
            int s = g_srcs1[base + lane];
            float4 pv = g_p1[base + lane];
            sbuf[lane] = s;
            pbuf[lane] = pv;
            den[0] += pv.x; den[1] += pv.y; den[2] += pv.z; den[3] += pv.w;
        }
        __syncwarp();
        for (int j = 0; j < n; j++) {
            int s = sbuf[j];
            cpa8((uint32_t)__cvta_generic_to_shared(buf + j * 128 + lane * 4),
                 g_xh + (size_t)s * IN_DIM + lane * 4);
        }
        CP_COMMIT();
        CP_WAIT0();
        __syncwarp();
        for (int j = 0; j < n; j++) {
            float4 pv = pbuf[j];     // LDS broadcast
            uint2 v = *(const uint2*)(buf + j * 128 + lane * 4);
            float2 f01 = __half22float2(*(__half2*)&v.x);
            float2 f23 = __half22float2(*(__half2*)&v.y);
            acc[0][0] = fmaf(pv.x, f01.x, acc[0][0]);
            acc[0][1] = fmaf(pv.x, f01.y, acc[0][1]);
            acc[0][2] = fmaf(pv.x, f23.x, acc[0][2]);
            acc[0][3] = fmaf(pv.x, f23.y, acc[0][3]);
            acc[1][0] = fmaf(pv.y, f01.x, acc[1][0]);
            acc[1][1] = fmaf(pv.y, f01.y, acc[1][1]);
            acc[1][2] = fmaf(pv.y, f23.x, acc[1][2]);
            acc[1][3] = fmaf(pv.y, f23.y, acc[1][3]);
            acc[2][0] = fmaf(pv.z, f01.x, acc[2][0]);
            acc[2][1] = fmaf(pv.z, f01.y, acc[2][1]);
            acc[2][2] = fmaf(pv.z, f23.x, acc[2][2]);
            acc[2][3] = fmaf(pv.z, f23.y, acc[2][3]);
            acc[3][0] = fmaf(pv.w, f01.x, acc[3][0]);
            acc[3][1] = fmaf(pv.w, f01.y, acc[3][1]);
            acc[3][2] = fmaf(pv.w, f23.x, acc[3][2]);
            acc[3][3] = fmaf(pv.w, f23.y, acc[3][3]);
        }
        __syncwarp();
    }
    #pragma unroll
    for (int h = 0; h < 4; h++) {
        float inv = 1.0f / fmaxf(wredsum(den[h]), 1e-16f);
        __half2 q0 = __floats2half2_rn(acc[h][0] * inv, acc[h][1] * inv);
        __half2 q1 = __floats2half2_rn(acc[h][2] * inv, acc[h][3] * inv);
        uint2 pkt;
        pkt.x = *(unsigned*)&q0;
        pkt.y = *(unsigned*)&q1;
        *(uint2*)(outp + h * IN_DIM + lane * 4) = pkt;
    }
}

// ============ launch 4: layer-1 HMMA GEMM + BN + ELU + fp16 store + a2 ======
__global__ void __launch_bounds__(256) k_out1(const float* __restrict__ b1) {
    __shared__ __align__(16) __half As[128 * 128];
    __shared__ __align__(16) __half Bs[64 * 128];
    int t = threadIdx.x;
    int d0 = blockIdx.x * 128;
    int head = blockIdx.y;

    {
        #pragma unroll
        for (int j = 0; j < 8; j++) {
            int i = j * 256 + t;
            int row = i >> 4, c = i & 15;
            uint4 v = *(const uint4*)(g_agg1h + (size_t)(d0 + row) * 512
                                      + head * IN_DIM + c * 8);
            *(uint4*)((char*)As + row * 256 + ((c ^ (row & 7)) << 4)) = v;
        }
        #pragma unroll
        for (int j = 0; j < 4; j++) {
            int i = j * 256 + t;
            int n = i >> 4, c = i & 15;
            uint4 v = *(const uint4*)(g_W1hT + (head * 64 + n) * IN_DIM + c * 8);
            *(uint4*)((char*)Bs + n * 256 + ((c ^ (n & 7)) << 4)) = v;
        }
    }
    __syncthreads();

    int lane = t & 31;
    int warp = t >> 5;
    int R = warp * 16;
    uint32_t as_base = (uint32_t)__cvta_generic_to_shared(As);
    uint32_t bs_base = (uint32_t)__cvta_generic_to_shared(Bs);

    float acc[8][4];
    #pragma unroll
    for (int nt = 0; nt < 8; nt++)
        #pragma unroll
        for (int c = 0; c < 4; c++) acc[nt][c] = 0.f;

    int grp = lane >> 3, rowin = lane & 7;
    #pragma unroll
    for (int ks = 0; ks < 8; ks++) {
        int kc = ks * 2;
        uint32_t a0, a1, a2, a3;
        {
            int row = R + rowin + ((grp & 1) << 3);
            int chunk = (kc + ((grp >> 1) & 1)) ^ (row & 7);
            ldsm_x4(a0, a1, a2, a3, as_base + row * 256 + (chunk << 4));
        }
        #pragma unroll
        for (int np = 0; np < 4; np++) {
            uint32_t b0, b1v, b2, b3;
            int n = np * 16 + rowin + ((grp >> 1) << 3);
            int chunk = (kc + (grp & 1)) ^ (n & 7);
            ldsm_x4(b0, b1v, b2, b3, bs_base + n * 256 + (chunk << 4));
            mma16816(acc[np * 2], a0, a1, a2, a3, b0, b1v);
            mma16816(acc[np * 2 + 1], a0, a1, a2, a3, b2, b3);
        }
    }

    int q = lane >> 2;
    int cpair = (lane & 3) * 2;
    int row_lo = d0 + R + q;
    int row_hi = row_lo + 8;
    float ps_lo = 0.f, pd_lo = 0.f, ps_hi = 0.f, pd_hi = 0.f;
    #pragma unroll
    for (int nt = 0; nt < 8; nt++) {
        int gc = head * 64 + nt * 8 + cpair;
        float2 bb = *(const float2*)&b1[gc];
        float2 sc = *(const float2*)&g_bnsc[gc];
        float2 sh = *(const float2*)&g_bnsh[gc];
        float2 vs = *(const float2*)&g_V2s[gc];
        float2 vd = *(const float2*)&g_V2d[gc];
        float v0 = (acc[nt][0] + bb.x) * sc.x + sh.x;
        float v1 = (acc[nt][1] + bb.y) * sc.y + sh.y;
        float v2 = (acc[nt][2] + bb.x) * sc.x + sh.x;
        float v3 = (acc[nt][3] + bb.y) * sc.y + sh.y;
        v0 = v0 > 0.f ? v0 : __expf(v0) - 1.f;
        v1 = v1 > 0.f ? v1 : __expf(v1) - 1.f;
        v2 = v2 > 0.f ? v2 : __expf(v2) - 1.f;
        v3 = v3 > 0.f ? v3 : __expf(v3) - 1.f;
        ps_lo = fmaf(v0, vs.x, fmaf(v1, vs.y, ps_lo));
        pd_lo = fmaf(v0, vd.x, fmaf(v1, vd.y, pd_lo));
        ps_hi = fmaf(v2, vs.x, fmaf(v3, vs.y, ps_hi));
        pd_hi = fmaf(v2, vd.x, fmaf(v3, vd.y, pd_hi));
        __half2 lo = __floats2half2_rn(v0, v1);
        __half2 hi = __floats2half2_rn(v2, v3);
        *(__half2*)(g_h1h + (size_t)row_lo * HD + gc) = lo;
        *(__half2*)(g_h1h + (size_t)row_hi * HD + gc) = hi;
    }
    #pragma unroll
    for (int m = 1; m < 4; m <<= 1) {
        ps_lo += __shfl_xor_sync(0xFFFFFFFFu, ps_lo, m);
        pd_lo += __shfl_xor_sync(0xFFFFFFFFu, pd_lo, m);
        ps_hi += __shfl_xor_sync(0xFFFFFFFFu, ps_hi, m);
        pd_hi += __shfl_xor_sync(0xFFFFFFFFu, pd_hi, m);
    }
    if ((lane & 3) == 0) {
        g_a2sp[row_lo * 4 + head] = ps_lo;
        g_a2sp[row_hi * 4 + head] = ps_hi;
        if (row_lo < N3) g_a2dp[row_lo * 4 + head] = pd_lo;
        if (row_hi < N3) g_a2dp[row_hi * 4 + head] = pd_hi;
    }
}

// ============ launch 5: layer-2 aggregate, cp.async staged (warp per dst) ==
#define M2_WARPS 8
#define M2_WBYTES (4096 + 32 + 32)
__global__ void __launch_bounds__(256) k_msg2() {
    extern __shared__ __align__(16) char sm2[];
    int t = threadIdx.x, lane = t & 31, wl = t >> 5;
    char* wbase = sm2 + wl * M2_WBYTES;
    __half* buf = (__half*)wbase;                // [8 edges][256 halves]
    float* pbuf = (float*)(wbase + 4096);        // [8]
    int*   sbuf = (int*)(wbase + 4096 + 32);     // [8]
    int w = blockIdx.x * M2_WARPS + wl;
    if (w >= N3) return;
    int start = g_rs2[w], end = g_rs2[w + 1];
    float* outp = g_agg2 + (size_t)w * HD;
    if (start == end) {
        float4 z = make_float4(0.f, 0.f, 0.f, 0.f);
        *(float4*)(outp + lane * 8) = z;
        *(float4*)(outp + lane * 8 + 4) = z;
        return;
    }
    float4 adv = *(const float4*)&g_a2dp[w * 4];
    float ad = adv.x + adv.y + adv.z + adv.w;
    float den = 0.f;
    float acc[8];
    #pragma unroll
    for (int f = 0; f < 8; f++) acc[f] = 0.f;

    for (int base = start; base < end; base += 8) {
        int n = min(8, end - base);
        if (lane < n) {
            int s = g_srcs2[base + lane];
            float4 sv = *(const float4*)&g_a2sp[s * 4];
            float e = sv.x + sv.y + sv.z + sv.w + ad;
            e = e > 0.f ? e : NEG_SLOPE * e;
            float p = __expf(e);
            sbuf[lane] = s;
            pbuf[lane] = p;
            den += p;
        }
        __syncwarp();
        for (int j = 0; j < n; j++) {
            int s = sbuf[j];
            cpa16((uint32_t)__cvta_generic_to_shared(buf + j * 256 + lane * 8),
                  g_h1h + (size_t)s * HD + lane * 8);
        }
        CP_COMMIT();
        CP_WAIT0();
        __syncwarp();
        for (int j = 0; j < n; j++) {
            float a = pbuf[j];
            uint4 v = *(const uint4*)(buf + j * 256 + lane * 8);
            float2 f0 = __half22float2(*(__half2*)&v.x);
            float2 f1 = __half22float2(*(__half2*)&v.y);
            float2 f2 = __half22float2(*(__half2*)&v.z);
            float2 f3 = __half22float2(*(__half2*)&v.w);
            acc[0] = fmaf(a, f0.x, acc[0]);
            acc[1] = fmaf(a, f0.y, acc[1]);
            acc[2] = fmaf(a, f1.x, acc[2]);
            acc[3] = fmaf(a, f1.y, acc[3]);
            acc[4] = fmaf(a, f2.x, acc[4]);
            acc[5] = fmaf(a, f2.y, acc[5]);
            acc[6] = fmaf(a, f3.x, acc[6]);
            acc[7] = fmaf(a, f3.y, acc[7]);
        }
        __syncwarp();
    }
    float inv = 1.0f / fmaxf(wredsum(den), 1e-16f);
    *(float4*)(outp + lane * 8) =
        make_float4(acc[0] * inv, acc[1] * inv, acc[2] * inv, acc[3] * inv);
    *(float4*)(outp + lane * 8 + 4) =
        make_float4(acc[4] * inv, acc[5] * inv, acc[6] * inv, acc[7] * inv);
}

// ============ launch 6: layer-2 output GEMM + b2 ============================
#define G2_ROWS 64
__global__ void k_out2(const float* __restrict__ W2s, const float* __restrict__ b2,
                       float* __restrict__ out) {
    extern __shared__ float sm[];
    float* Ws = sm;
    float* Ag = sm + HD * OUT_DIM;
    int t = threadIdx.x;  // 256
    for (int i = t; i < HD * OUT_DIM / 4; i += 256)
        ((float4*)Ws)[i] = ((const float4*)W2s)[i];
    int d0 = blockIdx.x * G2_ROWS;
    const float4* agg_src = (const float4*)(g_agg2 + (size_t)d0 * HD);
    for (int i = t; i < G2_ROWS * HD / 4; i += 256)
        ((float4*)Ag)[i] = agg_src[i];
    __syncthreads();

    int cg = (t & 15) * 4;
    int r0 = (t >> 4) * 4;
    float acc[4][4];
    #pragma unroll
    for (int r = 0; r < 4; r++)
        #pragma unroll
        for (int c = 0; c < 4; c++) acc[r][c] = 0.f;

    #pragma unroll 4
    for (int k = 0; k < HD; k++) {
        float4 wv = *(float4*)&Ws[k * OUT_DIM + cg];
        #pragma unroll
        for (int r = 0; r < 4; r++) {
            float a = Ag[(r0 + r) * HD + k];
            acc[r][0] = fmaf(a, wv.x, acc[r][0]);
            acc[r][1] = fmaf(a, wv.y, acc[r][1]);
            acc[r][2] = fmaf(a, wv.z, acc[r][2]);
            acc[r][3] = fmaf(a, wv.w, acc[r][3]);
        }
    }
    float4 bv = *(const float4*)&b2[cg];
    #pragma unroll
    for (int r = 0; r < 4; r++) {
        int d = d0 + r0 + r;
        float4 o = make_float4(acc[r][0] + bv.x, acc[r][1] + bv.y,
                               acc[r][2] + bv.z, acc[r][3] + bv.w);
        *(float4*)&out[(size_t)d * OUT_DIM + cg] = o;
    }
}

// ---------------- launch ----------------
extern "C" void kernel_launch(void* const* d_in, const int* in_sizes, int n_in,
                              void* d_out, int out_size) {
    const float* x     = (const float*)d_in[0];
    const float* W1s   = (const float*)d_in[1];
    const float* W1d   = (const float*)d_in[2];
    const float* att1s = (const float*)d_in[3];
    const float* att1d = (const float*)d_in[4];
    const float* b1    = (const float*)d_in[5];
    const float* gamma = (const float*)d_in[6];
    const float* beta  = (const float*)d_in[7];
    const float* rmean = (const float*)d_in[8];
    const float* rvar  = (const float*)d_in[9];
    const float* W2s   = (const float*)d_in[10];
    const float* W2d   = (const float*)d_in[11];
    const float* att2s = (const float*)d_in[12];
    const float* att2d = (const float*)d_in[13];
    const float* b2    = (const float*)d_in[14];
    const int* src1    = (const int*)d_in[15];
    const int* dst1    = (const int*)d_in[16];
    const int* src2    = (const int*)d_in[17];
    const int* dst2    = (const int*)d_in[18];
    float* out = (float*)d_out;

    cudaFuncSetAttribute(k_msg1, cudaFuncAttributeMaxDynamicSharedMemorySize,
                         M1_WARPS * M1_WBYTES);
    cudaFuncSetAttribute(k_msg2, cudaFuncAttributeMaxDynamicSharedMemorySize,
                         M2_WARPS * M2_WBYTES);
    cudaFuncSetAttribute(k_out2, cudaFuncAttributeMaxDynamicSharedMemorySize,
                         (HD * OUT_DIM + G2_ROWS * HD) * 4);

    // 0: histogram + fold + W1hT transpose
    k0_hist_fold<<<1545, 512>>>(dst1, dst2, W1s, W1d, att1s, att1d,
                                W2s, W2d, att2s, att2d, gamma, beta, rmean, rvar);
    // 1: scans (blocks 0,1) + a1 (blocks 2..513)
    k_scan_a1<<<2 + N1 / (16 * A1_ROWS), 512>>>(x);
    // 2: scatter + per-edge p + re-zero counters
    k2_scatter_zero<<<1536 + (N2 + N3) / 512, 512>>>(src1, dst1, src2, dst2);
    // 3: msg1  (ncu capture index 3)
    k_msg1<<<N2 / M1_WARPS, 256, M1_WARPS * M1_WBYTES>>>();
    // 4: out1 (HMMA)
    k_out1<<<dim3(N2 / 128, HEADS), 256>>>(b1);
    // 5: msg2
    k_msg2<<<N3 / M2_WARPS, 256, M2_WARPS * M2_WBYTES>>>();
    // 6: out2
    k_out2<<<N3 / G2_ROWS, 256, (HD * OUT_DIM + G2_ROWS * HD) * 4>>>(W2s, b2, out);
}